// round 16
// baseline (speedup 1.0000x reference)
#include <cuda_runtime.h>
#include <stdint.h>
#include <math.h>

#define B_  2
#define T_  2048
#define D_  1024
#define E_  8
#define H_  512
#define M_  2048
#define BT_ 4096
#define ST  4   // cp.async pipeline stages

// ---------------- scratch (device globals; no runtime allocation) ----------
// g_cnt starts zeroed (module load) and is re-zeroed at the END of k_combine
// each launch, so every kernel_launch entry sees g_cnt == 0.
__device__ __align__(16) float g_t1[(size_t)BT_ * H_];
__device__ __align__(16) float g_z [(size_t)M_  * H_];
__device__ __align__(16) float g_eo[(size_t)M_  * D_];   // expert out (pre-combine)
__device__ int   g_rowi[M_];
__device__ float g_sw[M_];
__device__ float g_ew[M_];
__device__ int   g_cnt[E_];
__device__ int   g_perm[E_ * M_];

__device__ __forceinline__ float sigmoidf_(float v) { return 1.0f / (1.0f + expf(-v)); }

__device__ __forceinline__ float tf32r(float v) {
    unsigned u; asm("cvt.rna.tf32.f32 %0, %1;" : "=r"(u) : "f"(v));
    return __uint_as_float(u);
}
__device__ __forceinline__ unsigned tf32u(float v) {
    unsigned u; asm("cvt.rna.tf32.f32 %0, %1;" : "=r"(u) : "f"(v));
    return u;
}
#define FU(x) __float_as_uint(x)

__device__ __forceinline__ void mma8(float* c, const unsigned* a, const unsigned* b) {
    asm volatile(
        "mma.sync.aligned.m16n8k8.row.col.f32.tf32.tf32.f32 "
        "{%0,%1,%2,%3}, {%4,%5,%6,%7}, {%8,%9}, {%0,%1,%2,%3};"
        : "+f"(c[0]), "+f"(c[1]), "+f"(c[2]), "+f"(c[3])
        : "r"(a[0]), "r"(a[1]), "r"(a[2]), "r"(a[3]), "r"(b[0]), "r"(b[1]));
}

__device__ __forceinline__ void cpa16(unsigned s, const void* g) {
    asm volatile("cp.async.cg.shared.global [%0], [%1], 16;" :: "r"(s), "l"(g));
}
__device__ __forceinline__ void cp_commit() { asm volatile("cp.async.commit_group;"); }
template<int N> __device__ __forceinline__ void cp_wait() {
    asm volatile("cp.async.wait_group %0;" :: "n"(N));
}
__device__ __forceinline__ unsigned sptr(const void* p) {
    return (unsigned)__cvta_generic_to_shared(p);
}

// ============================================================================
// K_GATE4: gating + expert grouping, 4 tokens per block (weights amortized).
// Per-token accumulation & reduction order identical to 1-token version.
// ============================================================================
__global__ __launch_bounds__(256) void k_gate4(
    const float* __restrict__ x,
    const int* __restrict__ ib, const int* __restrict__ it,
    const float* __restrict__ sgw, const float* __restrict__ sgb,
    const float* __restrict__ egw, const float* __restrict__ egb,
    const float* __restrict__ ebias)
{
    const int m0 = blockIdx.x * 4, tid = threadIdx.x;
    int rows[4];
    #pragma unroll
    for (int g2 = 0; g2 < 4; g2++) rows[g2] = ib[m0 + g2] * T_ + it[m0 + g2];

    float acc[4][9] = {};
    for (int d = tid; d < D_; d += 256) {
        float sg = sgw[d];
        float eg[E_];
        #pragma unroll
        for (int e = 0; e < E_; e++) eg[e] = egw[e * D_ + d];
        #pragma unroll
        for (int g2 = 0; g2 < 4; g2++) {
            float xv = x[(size_t)rows[g2] * D_ + d];
            acc[g2][0] = fmaf(xv, sg, acc[g2][0]);
            #pragma unroll
            for (int e = 0; e < E_; e++)
                acc[g2][1 + e] = fmaf(xv, eg[e], acc[g2][1 + e]);
        }
    }
    #pragma unroll
    for (int g2 = 0; g2 < 4; g2++)
        #pragma unroll
        for (int q = 0; q < 9; q++)
            #pragma unroll
            for (int o = 16; o; o >>= 1)
                acc[g2][q] += __shfl_xor_sync(0xffffffffu, acc[g2][q], o);

    __shared__ float red[8][4][9];
    int w = tid >> 5, ln = tid & 31;
    if (!ln) {
        #pragma unroll
        for (int g2 = 0; g2 < 4; g2++)
            #pragma unroll
            for (int q = 0; q < 9; q++) red[w][g2][q] = acc[g2][q];
    }
    __syncthreads();
    if (tid < 4) {
        const int g2 = tid, m = m0 + g2;
        float dots[9];
        #pragma unroll
        for (int q = 0; q < 9; q++) {
            float s = 0.f;
            #pragma unroll
            for (int ww = 0; ww < 8; ww++) s += red[ww][g2][q];
            dots[q] = s;
        }
        float ss = sigmoidf_(dots[0] + sgb[0]);
        float es[E_];
        float best = -1e30f; int bi = 0;
        #pragma unroll
        for (int e = 0; e < E_; e++) {
            es[e] = sigmoidf_(dots[1+e] + egb[e]);
            float sc = es[e] + ebias[e];
            if (sc > best) { best = sc; bi = e; }
        }
        float ts = es[bi];
        g_rowi[m] = rows[g2];
        g_sw[m] = sigmoidf_(ss - ts);
        g_ew[m] = sigmoidf_(ts - ss);
        int pos = atomicAdd(&g_cnt[bi], 1);
        g_perm[bi * M_ + pos] = m;
    }
}

// ============================================================================
// K_MLP1: fused first-layer dual GEMMs, phase-unrolled; ALL operands raw,
// cvt.rna applied at fragment load (bit-identical to pre-rounding).
//   z == E_ : shared branch, BM=128
//   z  < E_ : expert branch, BM=64 (gathered rows of raw x)
// ============================================================================
__global__ __launch_bounds__(256) void k_mlp1(
    const float* __restrict__ x,
    const float* __restrict__ w1, const float* __restrict__ b1,
    const float* __restrict__ w2, const float* __restrict__ b2,
    const float* __restrict__ ew1, const float* __restrict__ eb1,
    const float* __restrict__ ew2, const float* __restrict__ eb2)
{
    __shared__ __align__(16) float As [ST][128][16];
    __shared__ __align__(16) float B1s[ST][64][16];
    __shared__ __align__(16) float B2s[ST][64][16];
    __shared__ int sM[64], sR[64];

    const int tid  = threadIdx.x;
    const int col0 = blockIdx.y * 64;
    const int wid  = tid >> 5, lane = tid & 31;
    const int grp  = lane >> 2, tig = lane & 3;
    const int wn   = (wid >> 1) * 16;
    const int lr   = tid >> 2, lc = (tid & 3) * 4;
    const int kb   = 4 * tig;
    const int NK   = D_ / 16;   // 64

    if (blockIdx.z == E_) {
        const int row0 = blockIdx.x * 128;
        const int wm   = (wid & 1) * 64;

        const float* Ag0 = x  + (size_t)(row0 + lr) * D_ + lc;
        const float* Ag1 = Ag0 + (size_t)64 * D_;
        const float* B1g = w1 + (size_t)(col0 + lr) * D_ + lc;
        const float* B2g = w2 + (size_t)(col0 + lr) * D_ + lc;

        auto issue = [&](int s, int k0) {
            cpa16(sptr(&As [s][lr]     [lc]), Ag0 + k0);
            cpa16(sptr(&As [s][lr + 64][lc]), Ag1 + k0);
            cpa16(sptr(&B1s[s][lr]     [lc]), B1g + k0);
            cpa16(sptr(&B2s[s][lr]     [lc]), B2g + k0);
            cp_commit();
        };

        #pragma unroll
        for (int t = 0; t < ST - 1; t++) issue(t, t * 16);

        float acc1[4][2][4] = {}, acc2[4][2][4] = {};
        for (int t0 = 0; t0 < NK; t0 += ST) {
            #pragma unroll
            for (int u = 0; u < ST; u++) {
                const int t = t0 + u;
                cp_wait<ST - 2>();
                __syncthreads();
                if (t + ST - 1 < NK) issue((u + ST - 1) % ST, (t + ST - 1) * 16);
                else cp_commit();

                float4 alo[4], ahi[4], uu[2], vv[2];
                #pragma unroll
                for (int mi = 0; mi < 4; mi++) {
                    int r0 = wm + mi * 16 + grp;
                    alo[mi] = *(const float4*)&As[u][r0    ][kb];
                    ahi[mi] = *(const float4*)&As[u][r0 + 8][kb];
                }
                #pragma unroll
                for (int j = 0; j < 2; j++) {
                    int n = wn + j * 8 + grp;
                    uu[j] = *(const float4*)&B1s[u][n][kb];
                    vv[j] = *(const float4*)&B2s[u][n][kb];
                }
                unsigned a0[4][4], a1[4][4], bu0[2][2], bu1[2][2], bv0[2][2], bv1[2][2];
                #pragma unroll
                for (int mi = 0; mi < 4; mi++) {
                    a0[mi][0] = tf32u(alo[mi].x); a0[mi][1] = tf32u(ahi[mi].x);
                    a0[mi][2] = tf32u(alo[mi].y); a0[mi][3] = tf32u(ahi[mi].y);
                    a1[mi][0] = tf32u(alo[mi].z); a1[mi][1] = tf32u(ahi[mi].z);
                    a1[mi][2] = tf32u(alo[mi].w); a1[mi][3] = tf32u(ahi[mi].w);
                }
                #pragma unroll
                for (int j = 0; j < 2; j++) {
                    bu0[j][0] = tf32u(uu[j].x); bu0[j][1] = tf32u(uu[j].y);
                    bu1[j][0] = tf32u(uu[j].z); bu1[j][1] = tf32u(uu[j].w);
                    bv0[j][0] = tf32u(vv[j].x); bv0[j][1] = tf32u(vv[j].y);
                    bv1[j][0] = tf32u(vv[j].z); bv1[j][1] = tf32u(vv[j].w);
                }
                #pragma unroll
                for (int mi = 0; mi < 4; mi++)
                    #pragma unroll
                    for (int j = 0; j < 2; j++) {
                        mma8(acc1[mi][j], a0[mi], bu0[j]);
                        mma8(acc1[mi][j], a1[mi], bu1[j]);
                        mma8(acc2[mi][j], a0[mi], bv0[j]);
                        mma8(acc2[mi][j], a1[mi], bv1[j]);
                    }
            }
        }

        #pragma unroll
        for (int mi = 0; mi < 4; mi++) {
            #pragma unroll
            for (int j = 0; j < 2; j++) {
                int r = row0 + wm + mi * 16 + grp;
                int c = col0 + wn + j * 8 + 2 * tig;
                float bb1x = b1[c], bb1y = b1[c + 1];
                float bb2x = b2[c], bb2y = b2[c + 1];
                #pragma unroll
                for (int half = 0; half < 2; half++) {
                    int rr = r + half * 8;
                    float h1x = acc1[mi][j][half*2+0] + bb1x;
                    float h1y = acc1[mi][j][half*2+1] + bb1y;
                    float h2x = acc2[mi][j][half*2+0] + bb2x;
                    float h2y = acc2[mi][j][half*2+1] + bb2y;
                    float2 o;
                    o.x = h1x * sigmoidf_(h1x) * h2x;
                    o.y = h1y * sigmoidf_(h1y) * h2y;
                    *(float2*)&g_t1[(size_t)rr * H_ + c] = o;
                }
            }
        }
    } else {
        const int e = blockIdx.z;
        const int cnt = g_cnt[e];
        const int i0 = blockIdx.x * 64;
        if (i0 >= cnt) return;

        const int wm = (wid & 1) * 32;

        if (tid < 64) {
            int idx = i0 + tid; if (idx > cnt - 1) idx = cnt - 1;
            int m = g_perm[e * M_ + idx];
            sM[tid] = m; sR[tid] = g_rowi[m];
        }
        __syncthreads();

        const float* Ag  = x + (size_t)sR[lr] * D_ + lc;
        const float* B1g = ew1 + (size_t)e * H_ * D_ + (size_t)(col0 + lr) * D_ + lc;
        const float* B2g = ew2 + (size_t)e * H_ * D_ + (size_t)(col0 + lr) * D_ + lc;

        auto issue = [&](int s, int k0) {
            cpa16(sptr(&As [s][lr][lc]), Ag  + k0);
            cpa16(sptr(&B1s[s][lr][lc]), B1g + k0);
            cpa16(sptr(&B2s[s][lr][lc]), B2g + k0);
            cp_commit();
        };

        #pragma unroll
        for (int t = 0; t < ST - 1; t++) issue(t, t * 16);

        float acc1[2][2][4] = {}, acc2[2][2][4] = {};
        for (int t0 = 0; t0 < NK; t0 += ST) {
            #pragma unroll
            for (int u = 0; u < ST; u++) {
                const int t = t0 + u;
                cp_wait<ST - 2>();
                __syncthreads();
                if (t + ST - 1 < NK) issue((u + ST - 1) % ST, (t + ST - 1) * 16);
                else cp_commit();

                unsigned a0[2][4], a1[2][4];
                #pragma unroll
                for (int mi = 0; mi < 2; mi++) {
                    int r0 = wm + mi * 16 + grp;
                    float4 lo = *(const float4*)&As[u][r0    ][kb];
                    float4 hi = *(const float4*)&As[u][r0 + 8][kb];
                    a0[mi][0] = tf32u(lo.x); a0[mi][1] = tf32u(hi.x);
                    a0[mi][2] = tf32u(lo.y); a0[mi][3] = tf32u(hi.y);
                    a1[mi][0] = tf32u(lo.z); a1[mi][1] = tf32u(hi.z);
                    a1[mi][2] = tf32u(lo.w); a1[mi][3] = tf32u(hi.w);
                }
                unsigned bu0[2][2], bu1[2][2], bv0[2][2], bv1[2][2];
                #pragma unroll
                for (int j = 0; j < 2; j++) {
                    int n = wn + j * 8 + grp;
                    float4 uu = *(const float4*)&B1s[u][n][kb];
                    float4 vv = *(const float4*)&B2s[u][n][kb];
                    bu0[j][0] = tf32u(uu.x); bu0[j][1] = tf32u(uu.y);
                    bu1[j][0] = tf32u(uu.z); bu1[j][1] = tf32u(uu.w);
                    bv0[j][0] = tf32u(vv.x); bv0[j][1] = tf32u(vv.y);
                    bv1[j][0] = tf32u(vv.z); bv1[j][1] = tf32u(vv.w);
                }
                #pragma unroll
                for (int mi = 0; mi < 2; mi++)
                    #pragma unroll
                    for (int j = 0; j < 2; j++) {
                        mma8(acc1[mi][j], a0[mi], bu0[j]);
                        mma8(acc1[mi][j], a1[mi], bu1[j]);
                        mma8(acc2[mi][j], a0[mi], bv0[j]);
                        mma8(acc2[mi][j], a1[mi], bv1[j]);
                    }
            }
        }

        #pragma unroll
        for (int mi = 0; mi < 2; mi++) {
            #pragma unroll
            for (int j = 0; j < 2; j++) {
                int c = col0 + wn + j * 8 + 2 * tig;
                float bb1x = eb1[e*H_ + c], bb1y = eb1[e*H_ + c + 1];
                float bb2x = eb2[e*H_ + c], bb2y = eb2[e*H_ + c + 1];
                #pragma unroll
                for (int half = 0; half < 2; half++) {
                    int li  = wm + mi * 16 + grp + half * 8;
                    int idx = i0 + li;
                    if (idx < cnt) {
                        int m = sM[li];
                        float h1x = acc1[mi][j][half*2+0] + bb1x;
                        float h1y = acc1[mi][j][half*2+1] + bb1y;
                        float h2x = acc2[mi][j][half*2+0] + bb2x;
                        float h2y = acc2[mi][j][half*2+1] + bb2y;
                        float2 o;
                        o.x = h1x * sigmoidf_(h1x) * h2x;
                        o.y = h1y * sigmoidf_(h1y) * h2y;
                        *(float2*)&g_z[(size_t)m * H_ + c] = o;
                    }
                }
            }
        }
    }
}

// ============================================================================
// K_LN: rowwise LayerNorm (width 512), vectorized float4, 128 thr/row.
// ============================================================================
__global__ __launch_bounds__(128) void k_ln512v(
    const float* __restrict__ g0, const float* __restrict__ b0,
    const float* __restrict__ g1, const float* __restrict__ b1)
{
    const int r = blockIdx.x;
    float* p; const float *g, *b;
    if (r < BT_) { p = g_t1 + (size_t)r * H_;         g = g0; b = b0; }
    else         { p = g_z  + (size_t)(r - BT_) * H_; g = g1; b = b1; }

    const int tid = threadIdx.x;
    float4 v = ((const float4*)p)[tid];

    __shared__ float red1[4], red2[4];
    float s = v.x + v.y + v.z + v.w;
    #pragma unroll
    for (int o = 16; o; o >>= 1) s += __shfl_xor_sync(0xffffffffu, s, o);
    int w = tid >> 5, ln = tid & 31;
    if (!ln) red1[w] = s;
    __syncthreads();
    float mu = (red1[0] + red1[1] + red1[2] + red1[3]) * (1.0f / (float)H_);

    float dx = v.x - mu, dy = v.y - mu, dz = v.z - mu, dw = v.w - mu;
    float q = dx*dx + dy*dy + dz*dz + dw*dw;
    #pragma unroll
    for (int o = 16; o; o >>= 1) q += __shfl_xor_sync(0xffffffffu, q, o);
    if (!ln) red2[w] = q;
    __syncthreads();
    float rstd = rsqrtf((red2[0] + red2[1] + red2[2] + red2[3]) * (1.0f / (float)H_)
                        + 1e-5f);

    float4 gv = ((const float4*)g)[tid];
    float4 bv = ((const float4*)b)[tid];
    float4 o;
    o.x = tf32r(dx * rstd * gv.x + bv.x);
    o.y = tf32r(dy * rstd * gv.y + bv.y);
    o.z = tf32r(dz * rstd * gv.z + bv.z);
    o.w = tf32r(dw * rstd * gv.w + bv.w);
    ((float4*)p)[tid] = o;
}

// ============================================================================
// K_OUT2: fused output GEMMs, write-disjoint.
//   z == E_ : shared blocks, BM=128 BN=128: out[r] = g_t1[r]@sw3^T + b3 (cvt B)
//   z  < E_ : expert blocks, BM=64 BN=128:  g_eo[m] = g_z[m]@ew3[e]^T + eb3
// ============================================================================
__global__ __launch_bounds__(256) void k_out2(
    const float* __restrict__ w3, const float* __restrict__ b3,
    const float* __restrict__ ew3, const float* __restrict__ eb3,
    float* __restrict__ out)
{
    __shared__ __align__(16) float As[ST][128][16];
    __shared__ __align__(16) float Bs[ST][128][16];
    __shared__ int sM[64];

    const int tid  = threadIdx.x;
    const int col0 = blockIdx.y * 128;
    const int wid  = tid >> 5, lane = tid & 31;
    const int grp  = lane >> 2, tig = lane & 3;
    const int wn   = (wid >> 1) * 32;
    const int lr   = tid >> 2, lc = (tid & 3) * 4;
    const int kb   = 4 * tig;
    const int NK   = H_ / 16;   // 32

    if (blockIdx.z == E_) {
        const int row0 = blockIdx.x * 128;
        const int wm   = (wid & 1) * 64;

        const float* Ag0 = g_t1 + (size_t)(row0 + lr) * H_ + lc;
        const float* Ag1 = Ag0 + (size_t)64 * H_;
        const float* Bg0 = w3  + (size_t)(col0 + lr) * H_ + lc;
        const float* Bg1 = Bg0 + (size_t)64 * H_;

        auto issue = [&](int s, int k0) {
            cpa16(sptr(&As[s][lr]     [lc]), Ag0 + k0);
            cpa16(sptr(&As[s][lr + 64][lc]), Ag1 + k0);
            cpa16(sptr(&Bs[s][lr]     [lc]), Bg0 + k0);
            cpa16(sptr(&Bs[s][lr + 64][lc]), Bg1 + k0);
            cp_commit();
        };

        #pragma unroll
        for (int t = 0; t < ST - 1; t++) issue(t, t * 16);

        float acc[4][4][4] = {};
        for (int t0 = 0; t0 < NK; t0 += ST) {
            #pragma unroll
            for (int u = 0; u < ST; u++) {
                const int t = t0 + u;
                cp_wait<ST - 2>();
                __syncthreads();
                if (t + ST - 1 < NK) issue((u + ST - 1) % ST, (t + ST - 1) * 16);
                else cp_commit();

                float4 alo[4], ahi[4], bq[4];
                #pragma unroll
                for (int mi = 0; mi < 4; mi++) {
                    int r0 = wm + mi * 16 + grp;
                    alo[mi] = *(const float4*)&As[u][r0    ][kb];
                    ahi[mi] = *(const float4*)&As[u][r0 + 8][kb];
                }
                #pragma unroll
                for (int j = 0; j < 4; j++)
                    bq[j] = *(const float4*)&Bs[u][wn + j * 8 + grp][kb];

                unsigned a0[4][4], a1[4][4], b0[4][2], b1[4][2];
                #pragma unroll
                for (int mi = 0; mi < 4; mi++) {
                    a0[mi][0] = FU(alo[mi].x); a0[mi][1] = FU(ahi[mi].x);
                    a0[mi][2] = FU(alo[mi].y); a0[mi][3] = FU(ahi[mi].y);
                    a1[mi][0] = FU(alo[mi].z); a1[mi][1] = FU(ahi[mi].z);
                    a1[mi][2] = FU(alo[mi].w); a1[mi][3] = FU(ahi[mi].w);
                }
                #pragma unroll
                for (int j = 0; j < 4; j++) {
                    b0[j][0] = tf32u(bq[j].x); b0[j][1] = tf32u(bq[j].y);
                    b1[j][0] = tf32u(bq[j].z); b1[j][1] = tf32u(bq[j].w);
                }
                #pragma unroll
                for (int mi = 0; mi < 4; mi++)
                    #pragma unroll
                    for (int j = 0; j < 4; j++) {
                        mma8(acc[mi][j], a0[mi], b0[j]);
                        mma8(acc[mi][j], a1[mi], b1[j]);
                    }
            }
        }

        #pragma unroll
        for (int mi = 0; mi < 4; mi++) {
            #pragma unroll
            for (int j = 0; j < 4; j++) {
                int r = row0 + wm + mi * 16 + grp;
                int c = col0 + wn + j * 8 + 2 * tig;
                float bx = b3[c], by = b3[c + 1];
                #pragma unroll
                for (int half = 0; half < 2; half++) {
                    int rr = r + half * 8;
                    float2 o;
                    o.x = acc[mi][j][half*2+0] + bx;
                    o.y = acc[mi][j][half*2+1] + by;
                    *(float2*)&out[(size_t)rr * D_ + c] = o;
                }
            }
        }
    } else {
        const int e = blockIdx.z;
        const int cnt = g_cnt[e];
        const int i0 = blockIdx.x * 64;
        if (i0 >= cnt) return;

        const int wm = (wid & 1) * 32;

        if (tid < 64) {
            int idx = i0 + tid; if (idx > cnt - 1) idx = cnt - 1;
            sM[tid] = g_perm[e * M_ + idx];
        }
        __syncthreads();

        const float* Ag  = g_z + (size_t)sM[lr] * H_ + lc;
        const float* Bg0 = ew3 + (size_t)e * D_ * H_ + (size_t)(col0 + lr) * H_ + lc;
        const float* Bg1 = Bg0 + (size_t)64 * H_;

        auto issue = [&](int s, int k0) {
            cpa16(sptr(&As[s][lr]     [lc]), Ag  + k0);
            cpa16(sptr(&Bs[s][lr]     [lc]), Bg0 + k0);
            cpa16(sptr(&Bs[s][lr + 64][lc]), Bg1 + k0);
            cp_commit();
        };

        #pragma unroll
        for (int t = 0; t < ST - 1; t++) issue(t, t * 16);

        float acc[2][4][4] = {};
        for (int t0 = 0; t0 < NK; t0 += ST) {
            #pragma unroll
            for (int u = 0; u < ST; u++) {
                const int t = t0 + u;
                cp_wait<ST - 2>();
                __syncthreads();
                if (t + ST - 1 < NK) issue((u + ST - 1) % ST, (t + ST - 1) * 16);
                else cp_commit();

                unsigned a0[2][4], a1[2][4];
                #pragma unroll
                for (int mi = 0; mi < 2; mi++) {
                    int r0 = wm + mi * 16 + grp;
                    float4 lo = *(const float4*)&As[u][r0    ][kb];
                    float4 hi = *(const float4*)&As[u][r0 + 8][kb];
                    a0[mi][0] = FU(lo.x); a0[mi][1] = FU(hi.x);
                    a0[mi][2] = FU(lo.y); a0[mi][3] = FU(hi.y);
                    a1[mi][0] = FU(lo.z); a1[mi][1] = FU(hi.z);
                    a1[mi][2] = FU(lo.w); a1[mi][3] = FU(hi.w);
                }
                unsigned b0[4][2], b1[4][2];
                #pragma unroll
                for (int j = 0; j < 4; j++) {
                    float4 bq = *(const float4*)&Bs[u][wn + j * 8 + grp][kb];
                    b0[j][0] = tf32u(bq.x); b0[j][1] = tf32u(bq.y);
                    b1[j][0] = tf32u(bq.z); b1[j][1] = tf32u(bq.w);
                }
                #pragma unroll
                for (int mi = 0; mi < 2; mi++)
                    #pragma unroll
                    for (int j = 0; j < 4; j++) {
                        mma8(acc[mi][j], a0[mi], b0[j]);
                        mma8(acc[mi][j], a1[mi], b1[j]);
                    }
            }
        }

        #pragma unroll
        for (int mi = 0; mi < 2; mi++) {
            #pragma unroll
            for (int half = 0; half < 2; half++) {
                int li  = wm + mi * 16 + grp + half * 8;
                int idx = i0 + li;
                if (idx < cnt) {
                    int m = sM[li];
                    #pragma unroll
                    for (int j = 0; j < 4; j++) {
                        int c = col0 + wn + j * 8 + 2 * tig;
                        float2 o;
                        o.x = acc[mi][j][half*2+0] + eb3[e*D_ + c];
                        o.y = acc[mi][j][half*2+1] + eb3[e*D_ + c + 1];
                        *(float2*)&g_eo[(size_t)m * D_ + c] = o;
                    }
                }
            }
        }
    }
}

// ============================================================================
// K_COMBINE: out[row] = wsh*out[row] + wex*g_eo[m]; then re-zero g_cnt.
// ============================================================================
__global__ __launch_bounds__(256) void k_combine(float* __restrict__ out) {
    int i = blockIdx.x * 256 + threadIdx.x;    // < M_*D_/4
    int m = i >> 8;
    int c4 = i & 255;
    int row = g_rowi[m];
    float wsh = g_sw[m], wex = g_ew[m];
    float4 eo = ((const float4*)g_eo)[i];
    size_t o = (size_t)row * (D_ / 4) + c4;
    float4 cur = ((float4*)out)[o];
    cur.x = wsh * cur.x + wex * eo.x;
    cur.y = wsh * cur.y + wex * eo.y;
    cur.z = wsh * cur.z + wex * eo.z;
    cur.w = wsh * cur.w + wex * eo.w;
    ((float4*)out)[o] = cur;
    if (blockIdx.x == 0 && threadIdx.x < E_) g_cnt[threadIdx.x] = 0;
}

// ---------------- launch ----------------------------------------------------
extern "C" void kernel_launch(void* const* d_in, const int* in_sizes, int n_in,
                              void* d_out, int out_size)
{
    const float* x      = (const float*)d_in[0];
    const int*   ib     = (const int*)  d_in[1];
    const int*   it     = (const int*)  d_in[2];
    const float* sw1    = (const float*)d_in[3];
    const float* sb1    = (const float*)d_in[4];
    const float* sw2    = (const float*)d_in[5];
    const float* sb2    = (const float*)d_in[6];
    const float* sw3    = (const float*)d_in[7];
    const float* sb3    = (const float*)d_in[8];
    const float* slng   = (const float*)d_in[9];
    const float* slnb   = (const float*)d_in[10];
    const float* sgw    = (const float*)d_in[11];
    const float* sgb    = (const float*)d_in[12];
    const float* egw    = (const float*)d_in[13];
    const float* egb    = (const float*)d_in[14];
    const float* ebias  = (const float*)d_in[15];
    const float* ew1    = (const float*)d_in[16];
    const float* eb1    = (const float*)d_in[17];
    const float* ew2    = (const float*)d_in[18];
    const float* eb2    = (const float*)d_in[19];
    const float* ew3    = (const float*)d_in[20];
    const float* eb3    = (const float*)d_in[21];
    const float* selg   = (const float*)d_in[22];
    const float* selb   = (const float*)d_in[23];
    float* out = (float*)d_out;

    k_gate4<<<M_ / 4, 256>>>(x, ib, it, sgw, sgb, egw, egb, ebias);
    k_mlp1<<<dim3(32, 8, E_ + 1), 256>>>(x, sw1, sb1, sw2, sb2,
                                         ew1, eb1, ew2, eb2);
    k_ln512v<<<BT_ + M_, 128>>>(slng, slnb, selg, selb);
    k_out2<<<dim3(32, D_ / 128, E_ + 1), 256>>>(sw3, sb3, ew3, eb3, out);
    k_combine<<<(M_ * D_ / 4) / 256, 256>>>(out);
}

// round 17
// speedup vs baseline: 1.1347x; 1.1347x over previous
#include <cuda_runtime.h>
#include <stdint.h>
#include <math.h>

#define B_  2
#define T_  2048
#define D_  1024
#define E_  8
#define H_  512
#define M_  2048
#define BT_ 4096
#define ST  4   // cp.async pipeline stages

// ---------------- scratch (device globals; no runtime allocation) ----------
// g_cnt starts zeroed (module load) and is re-zeroed at the END of k_combine
// each launch, so every kernel_launch entry sees g_cnt == 0.
__device__ __align__(16) float g_xr [(size_t)BT_ * D_];  // tf32-rounded x
__device__ __align__(16) float g_w1r[(size_t)H_ * D_];   // tf32-rounded sw1
__device__ __align__(16) float g_w2r[(size_t)H_ * D_];   // tf32-rounded sw2
__device__ __align__(16) float g_w3r[(size_t)D_ * H_];   // tf32-rounded sw3
__device__ __align__(16) float g_t1[(size_t)BT_ * H_];
__device__ __align__(16) float g_z [(size_t)M_  * H_];
__device__ __align__(16) float g_eo[(size_t)M_  * D_];   // expert out (pre-combine)
__device__ int   g_rowi[M_];
__device__ float g_sw[M_];
__device__ float g_ew[M_];
__device__ int   g_cnt[E_];
__device__ int   g_perm[E_ * M_];

__device__ __forceinline__ float sigmoidf_(float v) { return 1.0f / (1.0f + expf(-v)); }

__device__ __forceinline__ float tf32r(float v) {
    unsigned u; asm("cvt.rna.tf32.f32 %0, %1;" : "=r"(u) : "f"(v));
    return __uint_as_float(u);
}
__device__ __forceinline__ unsigned tf32u(float v) {
    unsigned u; asm("cvt.rna.tf32.f32 %0, %1;" : "=r"(u) : "f"(v));
    return u;
}
#define FU(x) __float_as_uint(x)

__device__ __forceinline__ void mma8(float* c, const unsigned* a, const unsigned* b) {
    asm volatile(
        "mma.sync.aligned.m16n8k8.row.col.f32.tf32.tf32.f32 "
        "{%0,%1,%2,%3}, {%4,%5,%6,%7}, {%8,%9}, {%0,%1,%2,%3};"
        : "+f"(c[0]), "+f"(c[1]), "+f"(c[2]), "+f"(c[3])
        : "r"(a[0]), "r"(a[1]), "r"(a[2]), "r"(a[3]), "r"(b[0]), "r"(b[1]));
}

__device__ __forceinline__ void cpa16(unsigned s, const void* g) {
    asm volatile("cp.async.cg.shared.global [%0], [%1], 16;" :: "r"(s), "l"(g));
}
__device__ __forceinline__ void cp_commit() { asm volatile("cp.async.commit_group;"); }
template<int N> __device__ __forceinline__ void cp_wait() {
    asm volatile("cp.async.wait_group %0;" :: "n"(N));
}
__device__ __forceinline__ unsigned sptr(const void* p) {
    return (unsigned)__cvta_generic_to_shared(p);
}

// ============================================================================
// K0: round x + shared weights + GATING (4 tokens/block), one launch.
//   blocks [0, 4096)      -> round x (BT*D/4 float4)
//   blocks [4096, 4608)   -> round w1/w2/w3
//   blocks [4608, 5120)   -> gate tokens 4*(bx-4608) .. +3 (reads RAW x)
// g_cnt is guaranteed zero on entry (re-zeroed at end of k_combine).
// ============================================================================
#define RX_BLK ((BT_ * D_ / 4) / 256)   // 4096
#define RW_BLK ((H_ * D_ / 4) / 256)    // 512

__global__ __launch_bounds__(256) void k_round_gate(
    const float4* __restrict__ x4,
    const float4* __restrict__ w1, const float4* __restrict__ w2,
    const float4* __restrict__ w3,
    const int* __restrict__ ib, const int* __restrict__ it,
    const float* __restrict__ sgw, const float* __restrict__ sgb,
    const float* __restrict__ egw, const float* __restrict__ egb,
    const float* __restrict__ ebias)
{
    const int bx = blockIdx.x;
    const int tid = threadIdx.x;
    if (bx < RX_BLK) {
        int i = bx * 256 + tid;
        float4 v = x4[i];
        float4 o;
        o.x = tf32r(v.x); o.y = tf32r(v.y); o.z = tf32r(v.z); o.w = tf32r(v.w);
        ((float4*)g_xr)[i] = o;
    } else if (bx < RX_BLK + RW_BLK) {
        int i = (bx - RX_BLK) * 256 + tid;
        float4 a = w1[i], b = w2[i], c = w3[i];
        float4 oa, ob, oc;
        oa.x = tf32r(a.x); oa.y = tf32r(a.y); oa.z = tf32r(a.z); oa.w = tf32r(a.w);
        ob.x = tf32r(b.x); ob.y = tf32r(b.y); ob.z = tf32r(b.z); ob.w = tf32r(b.w);
        oc.x = tf32r(c.x); oc.y = tf32r(c.y); oc.z = tf32r(c.z); oc.w = tf32r(c.w);
        ((float4*)g_w1r)[i] = oa;
        ((float4*)g_w2r)[i] = ob;
        ((float4*)g_w3r)[i] = oc;
    } else {
        const int m0 = (bx - (RX_BLK + RW_BLK)) * 4;
        const float* x = (const float*)x4;
        int rows[4];
        #pragma unroll
        for (int g2 = 0; g2 < 4; g2++) rows[g2] = ib[m0 + g2] * T_ + it[m0 + g2];

        float acc[4][9] = {};
        for (int d = tid; d < D_; d += 256) {
            float sg = sgw[d];
            float eg[E_];
            #pragma unroll
            for (int e = 0; e < E_; e++) eg[e] = egw[e * D_ + d];
            #pragma unroll
            for (int g2 = 0; g2 < 4; g2++) {
                float xv = x[(size_t)rows[g2] * D_ + d];
                acc[g2][0] = fmaf(xv, sg, acc[g2][0]);
                #pragma unroll
                for (int e = 0; e < E_; e++)
                    acc[g2][1 + e] = fmaf(xv, eg[e], acc[g2][1 + e]);
            }
        }
        #pragma unroll
        for (int g2 = 0; g2 < 4; g2++)
            #pragma unroll
            for (int q = 0; q < 9; q++)
                #pragma unroll
                for (int o = 16; o; o >>= 1)
                    acc[g2][q] += __shfl_xor_sync(0xffffffffu, acc[g2][q], o);

        __shared__ float red[8][4][9];
        int w = tid >> 5, ln = tid & 31;
        if (!ln) {
            #pragma unroll
            for (int g2 = 0; g2 < 4; g2++)
                #pragma unroll
                for (int q = 0; q < 9; q++) red[w][g2][q] = acc[g2][q];
        }
        __syncthreads();
        if (tid < 4) {
            const int g2 = tid, m = m0 + g2;
            float dots[9];
            #pragma unroll
            for (int q = 0; q < 9; q++) {
                float s = 0.f;
                #pragma unroll
                for (int ww = 0; ww < 8; ww++) s += red[ww][g2][q];
                dots[q] = s;
            }
            float ss = sigmoidf_(dots[0] + sgb[0]);
            float es[E_];
            float best = -1e30f; int bi = 0;
            #pragma unroll
            for (int e = 0; e < E_; e++) {
                es[e] = sigmoidf_(dots[1+e] + egb[e]);
                float sc = es[e] + ebias[e];
                if (sc > best) { best = sc; bi = e; }
            }
            float ts = es[bi];
            g_rowi[m] = rows[g2];
            g_sw[m] = sigmoidf_(ss - ts);
            g_ew[m] = sigmoidf_(ts - ss);
            int pos = atomicAdd(&g_cnt[bi], 1);
            g_perm[bi * M_ + pos] = m;
        }
    }
}

// ============================================================================
// K_MLP1: fused first-layer dual GEMMs, phase-unrolled main loop.
//   z == E_ : shared branch, BM=128 (pre-rounded operands, no cvt)
//   z  < E_ : expert branch, BM=64 (rounded x, cvt expert weights inline)
// ============================================================================
__global__ __launch_bounds__(256) void k_mlp1(
    const float* __restrict__ b1,  const float* __restrict__ b2,
    const float* __restrict__ ew1, const float* __restrict__ eb1,
    const float* __restrict__ ew2, const float* __restrict__ eb2)
{
    __shared__ __align__(16) float As [ST][128][16];
    __shared__ __align__(16) float B1s[ST][64][16];
    __shared__ __align__(16) float B2s[ST][64][16];
    __shared__ int sM[64], sR[64];

    const int tid  = threadIdx.x;
    const int col0 = blockIdx.y * 64;
    const int wid  = tid >> 5, lane = tid & 31;
    const int grp  = lane >> 2, tig = lane & 3;
    const int wn   = (wid >> 1) * 16;
    const int lr   = tid >> 2, lc = (tid & 3) * 4;
    const int kb   = 4 * tig;
    const int NK   = D_ / 16;   // 64

    if (blockIdx.z == E_) {
        const int row0 = blockIdx.x * 128;
        const int wm   = (wid & 1) * 64;

        const float* Ag0 = g_xr  + (size_t)(row0 + lr) * D_ + lc;
        const float* Ag1 = Ag0 + (size_t)64 * D_;
        const float* B1g = g_w1r + (size_t)(col0 + lr) * D_ + lc;
        const float* B2g = g_w2r + (size_t)(col0 + lr) * D_ + lc;

        auto issue = [&](int s, int k0) {
            cpa16(sptr(&As [s][lr]     [lc]), Ag0 + k0);
            cpa16(sptr(&As [s][lr + 64][lc]), Ag1 + k0);
            cpa16(sptr(&B1s[s][lr]     [lc]), B1g + k0);
            cpa16(sptr(&B2s[s][lr]     [lc]), B2g + k0);
            cp_commit();
        };

        #pragma unroll
        for (int t = 0; t < ST - 1; t++) issue(t, t * 16);

        float acc1[4][2][4] = {}, acc2[4][2][4] = {};
        for (int t0 = 0; t0 < NK; t0 += ST) {
            #pragma unroll
            for (int u = 0; u < ST; u++) {
                const int t = t0 + u;
                cp_wait<ST - 2>();
                __syncthreads();
                if (t + ST - 1 < NK) issue((u + ST - 1) % ST, (t + ST - 1) * 16);
                else cp_commit();

                float4 alo[4], ahi[4], uu[2], vv[2];
                #pragma unroll
                for (int mi = 0; mi < 4; mi++) {
                    int r0 = wm + mi * 16 + grp;
                    alo[mi] = *(const float4*)&As[u][r0    ][kb];
                    ahi[mi] = *(const float4*)&As[u][r0 + 8][kb];
                }
                #pragma unroll
                for (int j = 0; j < 2; j++) {
                    int n = wn + j * 8 + grp;
                    uu[j] = *(const float4*)&B1s[u][n][kb];
                    vv[j] = *(const float4*)&B2s[u][n][kb];
                }
                unsigned a0[4][4], a1[4][4], bu0[2][2], bu1[2][2], bv0[2][2], bv1[2][2];
                #pragma unroll
                for (int mi = 0; mi < 4; mi++) {
                    a0[mi][0] = FU(alo[mi].x); a0[mi][1] = FU(ahi[mi].x);
                    a0[mi][2] = FU(alo[mi].y); a0[mi][3] = FU(ahi[mi].y);
                    a1[mi][0] = FU(alo[mi].z); a1[mi][1] = FU(ahi[mi].z);
                    a1[mi][2] = FU(alo[mi].w); a1[mi][3] = FU(ahi[mi].w);
                }
                #pragma unroll
                for (int j = 0; j < 2; j++) {
                    bu0[j][0] = FU(uu[j].x); bu0[j][1] = FU(uu[j].y);
                    bu1[j][0] = FU(uu[j].z); bu1[j][1] = FU(uu[j].w);
                    bv0[j][0] = FU(vv[j].x); bv0[j][1] = FU(vv[j].y);
                    bv1[j][0] = FU(vv[j].z); bv1[j][1] = FU(vv[j].w);
                }
                #pragma unroll
                for (int mi = 0; mi < 4; mi++)
                    #pragma unroll
                    for (int j = 0; j < 2; j++) {
                        mma8(acc1[mi][j], a0[mi], bu0[j]);
                        mma8(acc1[mi][j], a1[mi], bu1[j]);
                        mma8(acc2[mi][j], a0[mi], bv0[j]);
                        mma8(acc2[mi][j], a1[mi], bv1[j]);
                    }
            }
        }

        #pragma unroll
        for (int mi = 0; mi < 4; mi++) {
            #pragma unroll
            for (int j = 0; j < 2; j++) {
                int r = row0 + wm + mi * 16 + grp;
                int c = col0 + wn + j * 8 + 2 * tig;
                float bb1x = b1[c], bb1y = b1[c + 1];
                float bb2x = b2[c], bb2y = b2[c + 1];
                #pragma unroll
                for (int half = 0; half < 2; half++) {
                    int rr = r + half * 8;
                    float h1x = acc1[mi][j][half*2+0] + bb1x;
                    float h1y = acc1[mi][j][half*2+1] + bb1y;
                    float h2x = acc2[mi][j][half*2+0] + bb2x;
                    float h2y = acc2[mi][j][half*2+1] + bb2y;
                    float2 o;
                    o.x = h1x * sigmoidf_(h1x) * h2x;
                    o.y = h1y * sigmoidf_(h1y) * h2y;
                    *(float2*)&g_t1[(size_t)rr * H_ + c] = o;
                }
            }
        }
    } else {
        const int e = blockIdx.z;
        const int cnt = g_cnt[e];
        const int i0 = blockIdx.x * 64;
        if (i0 >= cnt) return;

        const int wm = (wid & 1) * 32;

        if (tid < 64) {
            int idx = i0 + tid; if (idx > cnt - 1) idx = cnt - 1;
            int m = g_perm[e * M_ + idx];
            sM[tid] = m; sR[tid] = g_rowi[m];
        }
        __syncthreads();

        const float* Ag  = g_xr + (size_t)sR[lr] * D_ + lc;
        const float* B1g = ew1 + (size_t)e * H_ * D_ + (size_t)(col0 + lr) * D_ + lc;
        const float* B2g = ew2 + (size_t)e * H_ * D_ + (size_t)(col0 + lr) * D_ + lc;

        auto issue = [&](int s, int k0) {
            cpa16(sptr(&As [s][lr][lc]), Ag  + k0);
            cpa16(sptr(&B1s[s][lr][lc]), B1g + k0);
            cpa16(sptr(&B2s[s][lr][lc]), B2g + k0);
            cp_commit();
        };

        #pragma unroll
        for (int t = 0; t < ST - 1; t++) issue(t, t * 16);

        float acc1[2][2][4] = {}, acc2[2][2][4] = {};
        for (int t0 = 0; t0 < NK; t0 += ST) {
            #pragma unroll
            for (int u = 0; u < ST; u++) {
                const int t = t0 + u;
                cp_wait<ST - 2>();
                __syncthreads();
                if (t + ST - 1 < NK) issue((u + ST - 1) % ST, (t + ST - 1) * 16);
                else cp_commit();

                unsigned a0[2][4], a1[2][4];
                #pragma unroll
                for (int mi = 0; mi < 2; mi++) {
                    int r0 = wm + mi * 16 + grp;
                    float4 lo = *(const float4*)&As[u][r0    ][kb];
                    float4 hi = *(const float4*)&As[u][r0 + 8][kb];
                    a0[mi][0] = FU(lo.x); a0[mi][1] = FU(hi.x);
                    a0[mi][2] = FU(lo.y); a0[mi][3] = FU(hi.y);
                    a1[mi][0] = FU(lo.z); a1[mi][1] = FU(hi.z);
                    a1[mi][2] = FU(lo.w); a1[mi][3] = FU(hi.w);
                }
                unsigned bu0[2][2], bu1[2][2], bv0[2][2], bv1[2][2];
                #pragma unroll
                for (int j = 0; j < 2; j++) {
                    int n = wn + j * 8 + grp;
                    float4 uu = *(const float4*)&B1s[u][n][kb];
                    float4 vv = *(const float4*)&B2s[u][n][kb];
                    bu0[j][0] = tf32u(uu.x); bu0[j][1] = tf32u(uu.y);
                    bu1[j][0] = tf32u(uu.z); bu1[j][1] = tf32u(uu.w);
                    bv0[j][0] = tf32u(vv.x); bv0[j][1] = tf32u(vv.y);
                    bv1[j][0] = tf32u(vv.z); bv1[j][1] = tf32u(vv.w);
                }
                #pragma unroll
                for (int mi = 0; mi < 2; mi++)
                    #pragma unroll
                    for (int j = 0; j < 2; j++) {
                        mma8(acc1[mi][j], a0[mi], bu0[j]);
                        mma8(acc1[mi][j], a1[mi], bu1[j]);
                        mma8(acc2[mi][j], a0[mi], bv0[j]);
                        mma8(acc2[mi][j], a1[mi], bv1[j]);
                    }
            }
        }

        #pragma unroll
        for (int mi = 0; mi < 2; mi++) {
            #pragma unroll
            for (int j = 0; j < 2; j++) {
                int c = col0 + wn + j * 8 + 2 * tig;
                float bb1x = eb1[e*H_ + c], bb1y = eb1[e*H_ + c + 1];
                float bb2x = eb2[e*H_ + c], bb2y = eb2[e*H_ + c + 1];
                #pragma unroll
                for (int half = 0; half < 2; half++) {
                    int li  = wm + mi * 16 + grp + half * 8;
                    int idx = i0 + li;
                    if (idx < cnt) {
                        int m = sM[li];
                        float h1x = acc1[mi][j][half*2+0] + bb1x;
                        float h1y = acc1[mi][j][half*2+1] + bb1y;
                        float h2x = acc2[mi][j][half*2+0] + bb2x;
                        float h2y = acc2[mi][j][half*2+1] + bb2y;
                        float2 o;
                        o.x = h1x * sigmoidf_(h1x) * h2x;
                        o.y = h1y * sigmoidf_(h1y) * h2y;
                        *(float2*)&g_z[(size_t)m * H_ + c] = o;
                    }
                }
            }
        }
    }
}

// ============================================================================
// K_LN: rowwise LayerNorm (width 512), vectorized float4, 128 thr/row.
// ============================================================================
__global__ __launch_bounds__(128) void k_ln512v(
    const float* __restrict__ g0, const float* __restrict__ b0,
    const float* __restrict__ g1, const float* __restrict__ b1)
{
    const int r = blockIdx.x;
    float* p; const float *g, *b;
    if (r < BT_) { p = g_t1 + (size_t)r * H_;         g = g0; b = b0; }
    else         { p = g_z  + (size_t)(r - BT_) * H_; g = g1; b = b1; }

    const int tid = threadIdx.x;
    float4 v = ((const float4*)p)[tid];

    __shared__ float red1[4], red2[4];
    float s = v.x + v.y + v.z + v.w;
    #pragma unroll
    for (int o = 16; o; o >>= 1) s += __shfl_xor_sync(0xffffffffu, s, o);
    int w = tid >> 5, ln = tid & 31;
    if (!ln) red1[w] = s;
    __syncthreads();
    float mu = (red1[0] + red1[1] + red1[2] + red1[3]) * (1.0f / (float)H_);

    float dx = v.x - mu, dy = v.y - mu, dz = v.z - mu, dw = v.w - mu;
    float q = dx*dx + dy*dy + dz*dz + dw*dw;
    #pragma unroll
    for (int o = 16; o; o >>= 1) q += __shfl_xor_sync(0xffffffffu, q, o);
    if (!ln) red2[w] = q;
    __syncthreads();
    float rstd = rsqrtf((red2[0] + red2[1] + red2[2] + red2[3]) * (1.0f / (float)H_)
                        + 1e-5f);

    float4 gv = ((const float4*)g)[tid];
    float4 bv = ((const float4*)b)[tid];
    float4 o;
    o.x = tf32r(dx * rstd * gv.x + bv.x);
    o.y = tf32r(dy * rstd * gv.y + bv.y);
    o.z = tf32r(dz * rstd * gv.z + bv.z);
    o.w = tf32r(dw * rstd * gv.w + bv.w);
    ((float4*)p)[tid] = o;
}

// ============================================================================
// K_OUT2: fused output GEMMs, write-disjoint.
//   z == E_ : shared blocks, BM=128 BN=128: out[r] = g_t1[r]@w3r^T + b3
//   z  < E_ : expert blocks, BM=64 BN=128:  g_eo[m] = g_z[m]@ew3[e]^T + eb3
// ============================================================================
__global__ __launch_bounds__(256) void k_out2(
    const float* __restrict__ b3,
    const float* __restrict__ ew3, const float* __restrict__ eb3,
    float* __restrict__ out)
{
    __shared__ __align__(16) float As[ST][128][16];
    __shared__ __align__(16) float Bs[ST][128][16];
    __shared__ int sM[64];

    const int tid  = threadIdx.x;
    const int col0 = blockIdx.y * 128;
    const int wid  = tid >> 5, lane = tid & 31;
    const int grp  = lane >> 2, tig = lane & 3;
    const int wn   = (wid >> 1) * 32;
    const int lr   = tid >> 2, lc = (tid & 3) * 4;
    const int kb   = 4 * tig;
    const int NK   = H_ / 16;   // 32

    if (blockIdx.z == E_) {
        const int row0 = blockIdx.x * 128;
        const int wm   = (wid & 1) * 64;

        const float* Ag0 = g_t1  + (size_t)(row0 + lr) * H_ + lc;
        const float* Ag1 = Ag0 + (size_t)64 * H_;
        const float* Bg0 = g_w3r + (size_t)(col0 + lr) * H_ + lc;
        const float* Bg1 = Bg0 + (size_t)64 * H_;

        auto issue = [&](int s, int k0) {
            cpa16(sptr(&As[s][lr]     [lc]), Ag0 + k0);
            cpa16(sptr(&As[s][lr + 64][lc]), Ag1 + k0);
            cpa16(sptr(&Bs[s][lr]     [lc]), Bg0 + k0);
            cpa16(sptr(&Bs[s][lr + 64][lc]), Bg1 + k0);
            cp_commit();
        };

        #pragma unroll
        for (int t = 0; t < ST - 1; t++) issue(t, t * 16);

        float acc[4][4][4] = {};
        for (int t0 = 0; t0 < NK; t0 += ST) {
            #pragma unroll
            for (int u = 0; u < ST; u++) {
                const int t = t0 + u;
                cp_wait<ST - 2>();
                __syncthreads();
                if (t + ST - 1 < NK) issue((u + ST - 1) % ST, (t + ST - 1) * 16);
                else cp_commit();

                float4 alo[4], ahi[4], bq[4];
                #pragma unroll
                for (int mi = 0; mi < 4; mi++) {
                    int r0 = wm + mi * 16 + grp;
                    alo[mi] = *(const float4*)&As[u][r0    ][kb];
                    ahi[mi] = *(const float4*)&As[u][r0 + 8][kb];
                }
                #pragma unroll
                for (int j = 0; j < 4; j++)
                    bq[j] = *(const float4*)&Bs[u][wn + j * 8 + grp][kb];

                unsigned a0[4][4], a1[4][4], b0[4][2], b1[4][2];
                #pragma unroll
                for (int mi = 0; mi < 4; mi++) {
                    a0[mi][0] = FU(alo[mi].x); a0[mi][1] = FU(ahi[mi].x);
                    a0[mi][2] = FU(alo[mi].y); a0[mi][3] = FU(ahi[mi].y);
                    a1[mi][0] = FU(alo[mi].z); a1[mi][1] = FU(ahi[mi].z);
                    a1[mi][2] = FU(alo[mi].w); a1[mi][3] = FU(ahi[mi].w);
                }
                #pragma unroll
                for (int j = 0; j < 4; j++) {
                    b0[j][0] = FU(bq[j].x); b0[j][1] = FU(bq[j].y);
                    b1[j][0] = FU(bq[j].z); b1[j][1] = FU(bq[j].w);
                }
                #pragma unroll
                for (int mi = 0; mi < 4; mi++)
                    #pragma unroll
                    for (int j = 0; j < 4; j++) {
                        mma8(acc[mi][j], a0[mi], b0[j]);
                        mma8(acc[mi][j], a1[mi], b1[j]);
                    }
            }
        }

        #pragma unroll
        for (int mi = 0; mi < 4; mi++) {
            #pragma unroll
            for (int j = 0; j < 4; j++) {
                int r = row0 + wm + mi * 16 + grp;
                int c = col0 + wn + j * 8 + 2 * tig;
                float bx = b3[c], by = b3[c + 1];
                #pragma unroll
                for (int half = 0; half < 2; half++) {
                    int rr = r + half * 8;
                    float2 o;
                    o.x = acc[mi][j][half*2+0] + bx;
                    o.y = acc[mi][j][half*2+1] + by;
                    *(float2*)&out[(size_t)rr * D_ + c] = o;
                }
            }
        }
    } else {
        const int e = blockIdx.z;
        const int cnt = g_cnt[e];
        const int i0 = blockIdx.x * 64;
        if (i0 >= cnt) return;

        const int wm = (wid & 1) * 32;

        if (tid < 64) {
            int idx = i0 + tid; if (idx > cnt - 1) idx = cnt - 1;
            sM[tid] = g_perm[e * M_ + idx];
        }
        __syncthreads();

        const float* Ag  = g_z + (size_t)sM[lr] * H_ + lc;
        const float* Bg0 = ew3 + (size_t)e * D_ * H_ + (size_t)(col0 + lr) * H_ + lc;
        const float* Bg1 = Bg0 + (size_t)64 * H_;

        auto issue = [&](int s, int k0) {
            cpa16(sptr(&As[s][lr]     [lc]), Ag  + k0);
            cpa16(sptr(&Bs[s][lr]     [lc]), Bg0 + k0);
            cpa16(sptr(&Bs[s][lr + 64][lc]), Bg1 + k0);
            cp_commit();
        };

        #pragma unroll
        for (int t = 0; t < ST - 1; t++) issue(t, t * 16);

        float acc[2][4][4] = {};
        for (int t0 = 0; t0 < NK; t0 += ST) {
            #pragma unroll
            for (int u = 0; u < ST; u++) {
                const int t = t0 + u;
                cp_wait<ST - 2>();
                __syncthreads();
                if (t + ST - 1 < NK) issue((u + ST - 1) % ST, (t + ST - 1) * 16);
                else cp_commit();

                unsigned a0[2][4], a1[2][4];
                #pragma unroll
                for (int mi = 0; mi < 2; mi++) {
                    int r0 = wm + mi * 16 + grp;
                    float4 lo = *(const float4*)&As[u][r0    ][kb];
                    float4 hi = *(const float4*)&As[u][r0 + 8][kb];
                    a0[mi][0] = FU(lo.x); a0[mi][1] = FU(hi.x);
                    a0[mi][2] = FU(lo.y); a0[mi][3] = FU(hi.y);
                    a1[mi][0] = FU(lo.z); a1[mi][1] = FU(hi.z);
                    a1[mi][2] = FU(lo.w); a1[mi][3] = FU(hi.w);
                }
                unsigned b0[4][2], b1[4][2];
                #pragma unroll
                for (int j = 0; j < 4; j++) {
                    float4 bq = *(const float4*)&Bs[u][wn + j * 8 + grp][kb];
                    b0[j][0] = tf32u(bq.x); b0[j][1] = tf32u(bq.y);
                    b1[j][0] = tf32u(bq.z); b1[j][1] = tf32u(bq.w);
                }
                #pragma unroll
                for (int mi = 0; mi < 2; mi++)
                    #pragma unroll
                    for (int j = 0; j < 4; j++) {
                        mma8(acc[mi][j], a0[mi], b0[j]);
                        mma8(acc[mi][j], a1[mi], b1[j]);
                    }
            }
        }

        #pragma unroll
        for (int mi = 0; mi < 2; mi++) {
            #pragma unroll
            for (int half = 0; half < 2; half++) {
                int li  = wm + mi * 16 + grp + half * 8;
                int idx = i0 + li;
                if (idx < cnt) {
                    int m = sM[li];
                    #pragma unroll
                    for (int j = 0; j < 4; j++) {
                        int c = col0 + wn + j * 8 + 2 * tig;
                        float2 o;
                        o.x = acc[mi][j][half*2+0] + eb3[e*D_ + c];
                        o.y = acc[mi][j][half*2+1] + eb3[e*D_ + c + 1];
                        *(float2*)&g_eo[(size_t)m * D_ + c] = o;
                    }
                }
            }
        }
    }
}

// ============================================================================
// K_COMBINE: out[row] = wsh*out[row] + wex*g_eo[m]; then re-zero g_cnt.
// ============================================================================
__global__ __launch_bounds__(256) void k_combine(float* __restrict__ out) {
    int i = blockIdx.x * 256 + threadIdx.x;    // < M_*D_/4
    int m = i >> 8;
    int c4 = i & 255;
    int row = g_rowi[m];
    float wsh = g_sw[m], wex = g_ew[m];
    float4 eo = ((const float4*)g_eo)[i];
    size_t o = (size_t)row * (D_ / 4) + c4;
    float4 cur = ((float4*)out)[o];
    cur.x = wsh * cur.x + wex * eo.x;
    cur.y = wsh * cur.y + wex * eo.y;
    cur.z = wsh * cur.z + wex * eo.z;
    cur.w = wsh * cur.w + wex * eo.w;
    ((float4*)out)[o] = cur;
    if (blockIdx.x == 0 && threadIdx.x < E_) g_cnt[threadIdx.x] = 0;
}

// ---------------- launch ----------------------------------------------------
extern "C" void kernel_launch(void* const* d_in, const int* in_sizes, int n_in,
                              void* d_out, int out_size)
{
    const float* x      = (const float*)d_in[0];
    const int*   ib     = (const int*)  d_in[1];
    const int*   it     = (const int*)  d_in[2];
    const float* sw1    = (const float*)d_in[3];
    const float* sb1    = (const float*)d_in[4];
    const float* sw2    = (const float*)d_in[5];
    const float* sb2    = (const float*)d_in[6];
    const float* sw3    = (const float*)d_in[7];
    const float* sb3    = (const float*)d_in[8];
    const float* slng   = (const float*)d_in[9];
    const float* slnb   = (const float*)d_in[10];
    const float* sgw    = (const float*)d_in[11];
    const float* sgb    = (const float*)d_in[12];
    const float* egw    = (const float*)d_in[13];
    const float* egb    = (const float*)d_in[14];
    const float* ebias  = (const float*)d_in[15];
    const float* ew1    = (const float*)d_in[16];
    const float* eb1    = (const float*)d_in[17];
    const float* ew2    = (const float*)d_in[18];
    const float* eb2    = (const float*)d_in[19];
    const float* ew3    = (const float*)d_in[20];
    const float* eb3    = (const float*)d_in[21];
    const float* selg   = (const float*)d_in[22];
    const float* selb   = (const float*)d_in[23];
    float* out = (float*)d_out;

    k_round_gate<<<RX_BLK + RW_BLK + M_ / 4, 256>>>(
        (const float4*)x, (const float4*)sw1, (const float4*)sw2,
        (const float4*)sw3, ib, it, sgw, sgb, egw, egb, ebias);
    k_mlp1<<<dim3(32, 8, E_ + 1), 256>>>(sb1, sb2, ew1, eb1, ew2, eb2);
    k_ln512v<<<BT_ + M_, 128>>>(slng, slnb, selg, selb);
    k_out2<<<dim3(32, D_ / 128, E_ + 1), 256>>>(sb3, ew3, eb3, out);
    k_combine<<<(M_ * D_ / 4) / 256, 256>>>(out);
}